// round 1
// baseline (speedup 1.0000x reference)
#include <cuda_runtime.h>
#include <math_constants.h>

// Problem dims (fixed by the reference: inputs [8,1024,512] f32, codebook [8192,512] f32)
#define N_ROWS   8192      // 8*1024 flattened input vectors
#define K_CODES  8192
#define D_DIM    512

// GEMM tiling
#define BM 128
#define BN 128
#define BK 16
#define TM 8
#define TN 8
#define NSPLIT 4           // split codebook across blockIdx.y

// Output layout: flattened tuple, fp32
// [quantized_st (4194304) | loss (1) | indices (8192) | min_distances (8192) | loss_commit (1)]
#define QUANT_OFF  0
#define LOSS_OFF   (N_ROWS * D_DIM)                 // 4194304
#define IDX_OFF    (LOSS_OFF + 1)                   // 4194305
#define MIND_OFF   (IDX_OFF + N_ROWS)               // 4202497
#define COMMIT_OFF (MIND_OFF + N_ROWS)              // 4210689

// Scratch (no allocations allowed -> device globals)
__device__ unsigned long long g_minpack[N_ROWS];
__device__ float g_cb_norm[K_CODES];
__device__ float g_row_partial[N_ROWS];

// Map float -> monotonically ordered uint (s is a real number, never NaN here)
__device__ __forceinline__ unsigned int float_to_ordered(float f) {
    unsigned int b = __float_as_uint(f);
    return (b & 0x80000000u) ? ~b : (b | 0x80000000u);
}
__device__ __forceinline__ float ordered_to_float(unsigned int k) {
    unsigned int b = (k & 0x80000000u) ? (k ^ 0x80000000u) : ~k;
    return __uint_as_float(b);
}

// ---------------------------------------------------------------------------
// Kernel 1: codebook squared norms (one warp per code row) + minpack init
// ---------------------------------------------------------------------------
__global__ __launch_bounds__(256) void vq_prep(const float* __restrict__ CB) {
    int warp = (blockIdx.x * blockDim.x + threadIdx.x) >> 5;
    int lane = threadIdx.x & 31;
    if (warp < K_CODES) {
        const float4* row = reinterpret_cast<const float4*>(CB + (size_t)warp * D_DIM);
        float s = 0.0f;
        #pragma unroll
        for (int i = 0; i < 4; ++i) {
            float4 v = row[lane + i * 32];
            s = fmaf(v.x, v.x, s);
            s = fmaf(v.y, v.y, s);
            s = fmaf(v.z, v.z, s);
            s = fmaf(v.w, v.w, s);
        }
        #pragma unroll
        for (int o = 16; o > 0; o >>= 1) s += __shfl_down_sync(0xFFFFFFFFu, s, o);
        if (lane == 0) g_cb_norm[warp] = s;
    }
    int gid = blockIdx.x * blockDim.x + threadIdx.x;
    if (gid < N_ROWS) g_minpack[gid] = 0xFFFFFFFFFFFFFFFFull;
}

// ---------------------------------------------------------------------------
// Kernel 2: fused GEMM (x . e^T) + running argmin over s = ||e||^2 - 2 x.e
// ---------------------------------------------------------------------------
__global__ __launch_bounds__(256, 2)
void vq_gemm_argmin(const float* __restrict__ X, const float* __restrict__ CB) {
    __shared__ float As[BK][BM];
    __shared__ float Bs[BK][BN];

    const int m0    = blockIdx.x * BM;
    const int split = blockIdx.y;
    const int tid   = threadIdx.x;
    const int tx    = tid & 15;          // 0..15, column group
    const int ty    = tid >> 4;          // 0..15, row group

    float runmin[TM];
    int   runidx[TM];
    #pragma unroll
    for (int i = 0; i < TM; ++i) { runmin[i] = CUDART_INF_F; runidx[i] = 0; }

    const int codes_per_split = K_CODES / NSPLIT;   // 2048
    const int ntiles = codes_per_split / BN;        // 16

    for (int nt = 0; nt < ntiles; ++nt) {
        const int n0 = split * codes_per_split + nt * BN;

        float acc[TM][TN];
        #pragma unroll
        for (int i = 0; i < TM; ++i)
            #pragma unroll
            for (int j = 0; j < TN; ++j) acc[i][j] = 0.0f;

        for (int k0 = 0; k0 < D_DIM; k0 += BK) {
            // load tiles: 128x16 each, 512 float4s, 256 threads -> 2 each
            #pragma unroll
            for (int r = 0; r < 2; ++r) {
                int i4   = tid + r * 256;       // 0..511
                int row  = i4 >> 2;             // 0..127
                int col4 = (i4 & 3) * 4;        // 0,4,8,12
                float4 va = *reinterpret_cast<const float4*>(
                    &X[(size_t)(m0 + row) * D_DIM + k0 + col4]);
                As[col4 + 0][row] = va.x;
                As[col4 + 1][row] = va.y;
                As[col4 + 2][row] = va.z;
                As[col4 + 3][row] = va.w;
                float4 vb = *reinterpret_cast<const float4*>(
                    &CB[(size_t)(n0 + row) * D_DIM + k0 + col4]);
                Bs[col4 + 0][row] = vb.x;
                Bs[col4 + 1][row] = vb.y;
                Bs[col4 + 2][row] = vb.z;
                Bs[col4 + 3][row] = vb.w;
            }
            __syncthreads();

            #pragma unroll
            for (int kk = 0; kk < BK; ++kk) {
                float4 a0 = *reinterpret_cast<const float4*>(&As[kk][ty * TM]);
                float4 a1 = *reinterpret_cast<const float4*>(&As[kk][ty * TM + 4]);
                float4 b0 = *reinterpret_cast<const float4*>(&Bs[kk][tx * TN]);
                float4 b1 = *reinterpret_cast<const float4*>(&Bs[kk][tx * TN + 4]);
                float a[TM] = {a0.x, a0.y, a0.z, a0.w, a1.x, a1.y, a1.z, a1.w};
                float b[TN] = {b0.x, b0.y, b0.z, b0.w, b1.x, b1.y, b1.z, b1.w};
                #pragma unroll
                for (int i = 0; i < TM; ++i)
                    #pragma unroll
                    for (int j = 0; j < TN; ++j)
                        acc[i][j] = fmaf(a[i], b[j], acc[i][j]);
            }
            __syncthreads();
        }

        // epilogue: s = ||e||^2 - 2 * dot ; running min per row
        #pragma unroll
        for (int j = 0; j < TN; ++j) {
            int col = n0 + tx * TN + j;
            float cbn = g_cb_norm[col];
            #pragma unroll
            for (int i = 0; i < TM; ++i) {
                float s = fmaf(-2.0f, acc[i][j], cbn);
                if (s < runmin[i]) { runmin[i] = s; runidx[i] = col; }
            }
        }
    }

    // merge: packed (ordered-float-key << 32 | idx); min -> smallest dist,
    // smallest index on exact ties (matches reference argmin behavior)
    #pragma unroll
    for (int i = 0; i < TM; ++i) {
        int row = m0 + ty * TM + i;
        unsigned long long p =
            ((unsigned long long)float_to_ordered(runmin[i]) << 32) |
            (unsigned int)runidx[i];
        atomicMin(&g_minpack[row], p);
    }
}

// ---------------------------------------------------------------------------
// Kernel 3: per-row decode -> gather codebook row, min_dist, index, (x-q)^2
// ---------------------------------------------------------------------------
__global__ __launch_bounds__(128) void vq_gather(const float* __restrict__ X,
                                                 const float* __restrict__ CB,
                                                 float* __restrict__ out) {
    __shared__ float red_xn[4];
    __shared__ float red_dx[4];
    const int n = blockIdx.x;
    const int t = threadIdx.x;

    unsigned long long p = g_minpack[n];
    unsigned int idxc = (unsigned int)(p & 0xFFFFFFFFull);
    float smin = ordered_to_float((unsigned int)(p >> 32));

    const float4* xr = reinterpret_cast<const float4*>(X + (size_t)n * D_DIM);
    const float4* qr = reinterpret_cast<const float4*>(CB + (size_t)idxc * D_DIM);
    float4 x4 = xr[t];
    float4 q4 = qr[t];
    // quantized_st is numerically equal to quantized
    reinterpret_cast<float4*>(out + QUANT_OFF)[(size_t)n * (D_DIM / 4) + t] = q4;

    float xn = x4.x * x4.x + x4.y * x4.y + x4.z * x4.z + x4.w * x4.w;
    float dxv = (x4.x - q4.x) * (x4.x - q4.x) + (x4.y - q4.y) * (x4.y - q4.y)
              + (x4.z - q4.z) * (x4.z - q4.z) + (x4.w - q4.w) * (x4.w - q4.w);

    #pragma unroll
    for (int o = 16; o > 0; o >>= 1) {
        xn  += __shfl_down_sync(0xFFFFFFFFu, xn, o);
        dxv += __shfl_down_sync(0xFFFFFFFFu, dxv, o);
    }
    int w = t >> 5;
    if ((t & 31) == 0) { red_xn[w] = xn; red_dx[w] = dxv; }
    __syncthreads();
    if (t == 0) {
        float XN = red_xn[0] + red_xn[1] + red_xn[2] + red_xn[3];
        float DX = red_dx[0] + red_dx[1] + red_dx[2] + red_dx[3];
        g_row_partial[n]   = DX;
        out[MIND_OFF + n]  = smin + XN;
        out[IDX_OFF + n]   = (float)idxc;
    }
}

// ---------------------------------------------------------------------------
// Kernel 4: deterministic final loss reduction
// ---------------------------------------------------------------------------
__global__ __launch_bounds__(256) void vq_loss(float* __restrict__ out) {
    __shared__ float red[256];
    int t = threadIdx.x;
    float s = 0.0f;
    for (int i = t; i < N_ROWS; i += 256) s += g_row_partial[i];
    red[t] = s;
    __syncthreads();
    #pragma unroll
    for (int o = 128; o > 0; o >>= 1) {
        if (t < o) red[t] += red[t + o];
        __syncthreads();
    }
    if (t == 0) {
        float S = red[0];                    // == loss_vq == loss_commit
        out[COMMIT_OFF] = S;
        out[LOSS_OFF]   = fmaf(0.25f, S, S); // commitment_cost*commit + vq
    }
}

// ---------------------------------------------------------------------------
extern "C" void kernel_launch(void* const* d_in, const int* in_sizes, int n_in,
                              void* d_out, int out_size) {
    const float* X  = (const float*)d_in[0];   // inputs  [8,1024,512]
    const float* CB = (const float*)d_in[1];   // codebook [8192,512]
    float* out = (float*)d_out;

    vq_prep<<<K_CODES / 8, 256>>>(CB);
    dim3 grid_gemm(N_ROWS / BM, NSPLIT);
    vq_gemm_argmin<<<grid_gemm, 256>>>(X, CB);
    vq_gather<<<N_ROWS, 128>>>(X, CB, out);
    vq_loss<<<1, 256>>>(out);
}

// round 3
// speedup vs baseline: 6.2397x; 6.2397x over previous
#include <cuda_runtime.h>
#include <cuda_bf16.h>
#include <cuda_fp16.h>
#include <cstdint>
#include <math_constants.h>

#define N_ROWS   8192
#define K_CODES  8192
#define D_DIM    512

// Output layout: [quantized (4194304) | loss (1) | indices (8192) | min_dist (8192) | loss_commit (1)]
#define QUANT_OFF  0
#define LOSS_OFF   (N_ROWS * D_DIM)
#define IDX_OFF    (LOSS_OFF + 1)
#define MIND_OFF   (IDX_OFF + N_ROWS)
#define COMMIT_OFF (MIND_OFF + N_ROWS)

// ---------------- device scratch (no allocations allowed) ----------------
__device__ __nv_bfloat16 g_Xb[N_ROWS * D_DIM];          // bf16 inputs
__device__ __nv_bfloat16 g_Eb[K_CODES * D_DIM];         // bf16 codebook
__device__ __half        g_D[(size_t)N_ROWS * K_CODES]; // approx s = cbn - 2*dot (134MB)
__device__ float         g_cbn[K_CODES];
__device__ float         g_xn[N_ROWS];
__device__ float         g_row_partial[N_ROWS];

// ---------------- helpers ----------------
__device__ __forceinline__ uint32_t smem_u32(const void* p) {
    uint32_t a;
    asm("{ .reg .u64 t; cvta.to.shared.u64 t, %1; cvt.u32.u64 %0, t; }" : "=r"(a) : "l"(p));
    return a;
}
#define CP16(dst, src) \
    asm volatile("cp.async.cg.shared.global [%0], [%1], 16;" :: "r"(dst), "l"(src))
#define CP_COMMIT() asm volatile("cp.async.commit_group;" ::: "memory")
#define CP_WAIT1()  asm volatile("cp.async.wait_group 1;" ::: "memory")
#define CP_WAIT0()  asm volatile("cp.async.wait_group 0;" ::: "memory")

#define LDSM4(r0, r1, r2, r3, addr) \
    asm volatile("ldmatrix.sync.aligned.m8n8.x4.shared.b16 {%0,%1,%2,%3}, [%4];" \
        : "=r"(r0), "=r"(r1), "=r"(r2), "=r"(r3) : "r"(addr))

#define MMA16816(c, a, b0, b1) \
    asm volatile("mma.sync.aligned.m16n8k16.row.col.f32.bf16.bf16.f32 " \
        "{%0,%1,%2,%3}, {%4,%5,%6,%7}, {%8,%9}, {%0,%1,%2,%3};" \
        : "+f"((c)[0]), "+f"((c)[1]), "+f"((c)[2]), "+f"((c)[3]) \
        : "r"((a)[0]), "r"((a)[1]), "r"((a)[2]), "r"((a)[3]), "r"(b0), "r"(b1))

__device__ __forceinline__ unsigned int f2ord(float f) {
    unsigned int b = __float_as_uint(f);
    return (b & 0x80000000u) ? ~b : (b | 0x80000000u);
}
__device__ __forceinline__ float ord2f(unsigned int k) {
    unsigned int b = (k & 0x80000000u) ? (k ^ 0x80000000u) : ~k;
    return __uint_as_float(b);
}

// ---------------------------------------------------------------------------
// Kernel 1: fp32 -> bf16 conversion + row norms (one warp per row)
// ---------------------------------------------------------------------------
__global__ __launch_bounds__(256) void vq_prep(const float* __restrict__ X,
                                               const float* __restrict__ CB) {
    int row = blockIdx.x * 8 + (threadIdx.x >> 5);
    int lane = threadIdx.x & 31;
    bool isX = row < N_ROWS;
    const float* src = isX ? X + (size_t)row * D_DIM : CB + (size_t)(row - N_ROWS) * D_DIM;
    __nv_bfloat16* dst = isX ? g_Xb + (size_t)row * D_DIM : g_Eb + (size_t)(row - N_ROWS) * D_DIM;
    float nrm = 0.0f;
    #pragma unroll
    for (int i = 0; i < 4; ++i) {
        float4 v = reinterpret_cast<const float4*>(src)[lane + i * 32];
        nrm = fmaf(v.x, v.x, nrm); nrm = fmaf(v.y, v.y, nrm);
        nrm = fmaf(v.z, v.z, nrm); nrm = fmaf(v.w, v.w, nrm);
        __nv_bfloat162 b0 = __floats2bfloat162_rn(v.x, v.y);
        __nv_bfloat162 b1 = __floats2bfloat162_rn(v.z, v.w);
        uint2 pk;
        pk.x = *reinterpret_cast<uint32_t*>(&b0);
        pk.y = *reinterpret_cast<uint32_t*>(&b1);
        reinterpret_cast<uint2*>(dst)[lane + i * 32] = pk;
    }
    #pragma unroll
    for (int o = 16; o > 0; o >>= 1) nrm += __shfl_down_sync(0xFFFFFFFFu, nrm, o);
    if (lane == 0) {
        if (isX) g_xn[row] = nrm;
        else     g_cbn[row - N_ROWS] = nrm;
    }
}

// ---------------------------------------------------------------------------
// Kernel 2: bf16 mma.sync GEMM -> half score matrix g_D (s = cbn - 2*dot)
// CTA: 128x128 tile, 256 threads = 8 warps (2 m x 4 n), warp tile 64x32.
// BK=32, cp.async double buffered. Smem rows padded to 80B (conflict-free LDSM).
// ---------------------------------------------------------------------------
#define BKB      32
#define ROW_STR  80                            // 32 bf16 = 64B data + 16B pad
#define TILE_BYTES (128 * ROW_STR)             // 10240 per matrix
#define BUF_BYTES  (2 * TILE_BYTES)            // A+B per stage

__global__ __launch_bounds__(256) void vq_gemm() {
    __shared__ __align__(128) char smem[2 * BUF_BYTES];   // 40KB
    const uint32_t sb = smem_u32(smem);
    const int tid = threadIdx.x;
    const int wid = tid >> 5;
    const int lane = tid & 31;
    const int warp_m = wid >> 2;               // 0..1
    const int warp_n = wid & 3;                // 0..3
    const int m0 = blockIdx.x * 128;
    const int n0 = blockIdx.y * 128;

    float acc[4][4][4];
    #pragma unroll
    for (int i = 0; i < 4; ++i)
        #pragma unroll
        for (int j = 0; j < 4; ++j)
            #pragma unroll
            for (int q = 0; q < 4; ++q) acc[i][j][q] = 0.0f;

    // prefetch helper (as lambda-free macro-ish code): stage st, k offset k0
    const int c0 = tid;                        // chunks c0 and c0+256
    #define PREFETCH(st, k0)                                                          \
    do {                                                                              \
        uint32_t base = sb + (st) * BUF_BYTES;                                        \
        int c, row, kc;                                                               \
        c = c0;       row = c >> 2; kc = c & 3;                                       \
        CP16(base + row * ROW_STR + kc * 16,                                          \
             g_Xb + (size_t)(m0 + row) * D_DIM + (k0) + kc * 8);                      \
        CP16(base + TILE_BYTES + row * ROW_STR + kc * 16,                             \
             g_Eb + (size_t)(n0 + row) * D_DIM + (k0) + kc * 8);                      \
        c = c0 + 256; row = c >> 2; kc = c & 3;                                       \
        CP16(base + row * ROW_STR + kc * 16,                                          \
             g_Xb + (size_t)(m0 + row) * D_DIM + (k0) + kc * 8);                      \
        CP16(base + TILE_BYTES + row * ROW_STR + kc * 16,                             \
             g_Eb + (size_t)(n0 + row) * D_DIM + (k0) + kc * 8);                      \
        CP_COMMIT();                                                                  \
    } while (0)

    PREFETCH(0, 0);

    const int NSTEP = D_DIM / BKB;             // 16
    for (int s = 0; s < NSTEP; ++s) {
        if (s + 1 < NSTEP) {
            PREFETCH((s + 1) & 1, (s + 1) * BKB);
            CP_WAIT1();
        } else {
            CP_WAIT0();
        }
        __syncthreads();

        const uint32_t abase = sb + (s & 1) * BUF_BYTES;
        const uint32_t bbase = abase + TILE_BYTES;

        #pragma unroll
        for (int kk = 0; kk < 2; ++kk) {       // two k16 steps within BK=32
            uint32_t a[4][4], b[2][4];
            #pragma unroll
            for (int mi = 0; mi < 4; ++mi) {
                uint32_t addr = abase
                    + (uint32_t)(warp_m * 64 + mi * 16 + (lane & 15)) * ROW_STR
                    + (uint32_t)((lane >> 4) + kk * 2) * 16;
                LDSM4(a[mi][0], a[mi][1], a[mi][2], a[mi][3], addr);
            }
            #pragma unroll
            for (int nj = 0; nj < 2; ++nj) {
                uint32_t addr = bbase
                    + (uint32_t)(warp_n * 32 + nj * 16 + (lane & 7) + ((lane >> 4) * 8)) * ROW_STR
                    + (uint32_t)(((lane >> 3) & 1) + kk * 2) * 16;
                LDSM4(b[nj][0], b[nj][1], b[nj][2], b[nj][3], addr);
            }
            #pragma unroll
            for (int mi = 0; mi < 4; ++mi)
                #pragma unroll
                for (int ni = 0; ni < 4; ++ni)
                    MMA16816(acc[mi][ni], a[mi],
                             b[ni >> 1][(ni & 1) * 2], b[ni >> 1][(ni & 1) * 2 + 1]);
        }
        __syncthreads();
    }

    // epilogue: s = cbn - 2*dot -> half, direct store
    const int rbase = m0 + warp_m * 64 + (lane >> 2);
    const int cbase = n0 + warp_n * 32 + (lane & 3) * 2;
    #pragma unroll
    for (int ni = 0; ni < 4; ++ni) {
        const float2 cbn2 = *reinterpret_cast<const float2*>(&g_cbn[cbase + ni * 8]);
        #pragma unroll
        for (int mi = 0; mi < 4; ++mi) {
            float s0 = fmaf(-2.0f, acc[mi][ni][0], cbn2.x);
            float s1 = fmaf(-2.0f, acc[mi][ni][1], cbn2.y);
            float s2 = fmaf(-2.0f, acc[mi][ni][2], cbn2.x);
            float s3 = fmaf(-2.0f, acc[mi][ni][3], cbn2.y);
            __half2 h01 = __floats2half2_rn(s0, s1);
            __half2 h23 = __floats2half2_rn(s2, s3);
            size_t off = (size_t)(rbase + mi * 16) * K_CODES + cbase + ni * 8;
            *reinterpret_cast<__half2*>(g_D + off) = h01;
            *reinterpret_cast<__half2*>(g_D + off + (size_t)8 * K_CODES) = h23;
        }
    }
}

// ---------------------------------------------------------------------------
// Kernel 3: per-row argmin with exact fp32 rescoring of near-min candidates
// ---------------------------------------------------------------------------
#define MARGIN 4.0f
#define MAXCAND 64

__global__ __launch_bounds__(256) void vq_select(const float* __restrict__ X,
                                                 const float* __restrict__ CB,
                                                 float* __restrict__ out) {
    __shared__ float xrow[D_DIM];
    __shared__ unsigned long long redm[8];
    __shared__ float redf[8];
    __shared__ float redf2[8];
    __shared__ int cand[MAXCAND];
    __shared__ int cand_cnt;
    __shared__ unsigned long long best;
    __shared__ float thr_sh;

    const int n = blockIdx.x;
    const int t = threadIdx.x;
    const int w = t >> 5;
    const int lane = t & 31;

    float2 xv = reinterpret_cast<const float2*>(X + (size_t)n * D_DIM)[t];
    xrow[2 * t] = xv.x;
    xrow[2 * t + 1] = xv.y;
    if (t == 0) { cand_cnt = 0; best = 0xFFFFFFFFFFFFFFFFull; }

    // pass 1: scan half score row (s stored directly), find estimated min
    const uint4* dr = reinterpret_cast<const uint4*>(g_D + (size_t)n * K_CODES);
    float lmin = CUDART_INF_F;
    int lidx = 0;
    #pragma unroll
    for (int it = 0; it < 4; ++it) {
        int chunk = t + it * 256;
        uint4 v = dr[chunk];
        const uint32_t pk[4] = {v.x, v.y, v.z, v.w};
        #pragma unroll
        for (int q = 0; q < 4; ++q) {
            float2 d2 = __half22float2(*reinterpret_cast<const __half2*>(&pk[q]));
            int j0 = chunk * 8 + q * 2;
            if (d2.x < lmin) { lmin = d2.x; lidx = j0; }
            if (d2.y < lmin) { lmin = d2.y; lidx = j0 + 1; }
        }
    }
    unsigned long long pk = ((unsigned long long)f2ord(lmin) << 32) | (unsigned int)lidx;
    #pragma unroll
    for (int o = 16; o > 0; o >>= 1) {
        unsigned long long other = __shfl_down_sync(0xFFFFFFFFu, pk, o);
        if (other < pk) pk = other;
    }
    if (lane == 0) redm[w] = pk;
    __syncthreads();
    if (t == 0) {
        unsigned long long m = redm[0];
        #pragma unroll
        for (int i = 1; i < 8; ++i) if (redm[i] < m) m = redm[i];
        thr_sh = ord2f((unsigned int)(m >> 32)) + MARGIN;
    }
    __syncthreads();
    const float thr = thr_sh;

    // pass 2: collect candidates within margin (rows L1-hot)
    #pragma unroll
    for (int it = 0; it < 4; ++it) {
        int chunk = t + it * 256;
        uint4 v = dr[chunk];
        const uint32_t pkk[4] = {v.x, v.y, v.z, v.w};
        #pragma unroll
        for (int q = 0; q < 4; ++q) {
            float2 d2 = __half22float2(*reinterpret_cast<const __half2*>(&pkk[q]));
            int j0 = chunk * 8 + q * 2;
            if (d2.x <= thr) { int p = atomicAdd(&cand_cnt, 1); if (p < MAXCAND) cand[p] = j0; }
            if (d2.y <= thr) { int p = atomicAdd(&cand_cnt, 1); if (p < MAXCAND) cand[p] = j0 + 1; }
        }
    }
    __syncthreads();
    const int nc = min(cand_cnt, MAXCAND);

    // exact fp32 rescoring
    for (int c = 0; c < nc; ++c) {
        int j = cand[c];
        float2 e2 = reinterpret_cast<const float2*>(CB + (size_t)j * D_DIM)[t];
        float part = fmaf(xrow[2 * t], e2.x, xrow[2 * t + 1] * e2.y);
        #pragma unroll
        for (int o = 16; o > 0; o >>= 1) part += __shfl_down_sync(0xFFFFFFFFu, part, o);
        if (lane == 0) redf[w] = part;
        __syncthreads();
        if (t == 0) {
            float dot = redf[0] + redf[1] + redf[2] + redf[3]
                      + redf[4] + redf[5] + redf[6] + redf[7];
            float s = fmaf(-2.0f, dot, g_cbn[j]);
            unsigned long long p = ((unsigned long long)f2ord(s) << 32) | (unsigned int)j;
            if (p < best) best = p;
        }
        __syncthreads();
    }

    const unsigned long long bw = best;
    const int jstar = (int)(bw & 0xFFFFFFFFull);
    const float sstar = ord2f((unsigned int)(bw >> 32));

    float2 q2 = reinterpret_cast<const float2*>(CB + (size_t)jstar * D_DIM)[t];
    reinterpret_cast<float2*>(out + QUANT_OFF)[(size_t)n * (D_DIM / 2) + t] = q2;
    float d0 = xrow[2 * t] - q2.x;
    float d1 = xrow[2 * t + 1] - q2.y;
    float dl = fmaf(d0, d0, d1 * d1);
    #pragma unroll
    for (int o = 16; o > 0; o >>= 1) dl += __shfl_down_sync(0xFFFFFFFFu, dl, o);
    if (lane == 0) redf2[w] = dl;
    __syncthreads();
    if (t == 0) {
        float DL = redf2[0] + redf2[1] + redf2[2] + redf2[3]
                 + redf2[4] + redf2[5] + redf2[6] + redf2[7];
        g_row_partial[n] = DL;
        out[MIND_OFF + n] = g_xn[n] + sstar;
        out[IDX_OFF + n] = (float)jstar;
    }
}

// ---------------------------------------------------------------------------
// Kernel 4: final loss reduction
// ---------------------------------------------------------------------------
__global__ __launch_bounds__(256) void vq_loss(float* __restrict__ out) {
    __shared__ float red[256];
    int t = threadIdx.x;
    float s = 0.0f;
    for (int i = t; i < N_ROWS; i += 256) s += g_row_partial[i];
    red[t] = s;
    __syncthreads();
    #pragma unroll
    for (int o = 128; o > 0; o >>= 1) {
        if (t < o) red[t] += red[t + o];
        __syncthreads();
    }
    if (t == 0) {
        float S = red[0];
        out[COMMIT_OFF] = S;
        out[LOSS_OFF]   = fmaf(0.25f, S, S);
    }
}

// ---------------------------------------------------------------------------
extern "C" void kernel_launch(void* const* d_in, const int* in_sizes, int n_in,
                              void* d_out, int out_size) {
    const float* X  = (const float*)d_in[0];
    const float* CB = (const float*)d_in[1];
    float* out = (float*)d_out;

    vq_prep<<<(N_ROWS + K_CODES) / 8, 256>>>(X, CB);
    vq_gemm<<<dim3(64, 64), 256>>>();
    vq_select<<<N_ROWS, 256>>>(X, CB, out);
    vq_loss<<<1, 256>>>(out);
}